// round 4
// baseline (speedup 1.0000x reference)
#include <cuda_runtime.h>
#include <cuda_bf16.h>
#include <math.h>
#include <stdint.h>

#define NL   8
#define D_   768
#define E_   1536
#define N_   16
#define K_   4
#define DTR_ 48
#define B_   2
#define L_   2048
#define SSMW (DTR_ + 2*N_)   /* 80 */
#define ML   (B_*L_)         /* 4096 rows */

// ---------------- static scratch ----------------
__device__ float g_h   [ML * D_];
__device__ float g_proj[ML * 2 * E_];
__device__ float g_u   [ML * E_];
__device__ float g_ssm [ML * SSMW];
__device__ float g_dt  [ML * E_];

// bf16 hi|lo pair activations: row stride = 2*Ksz
__device__ __nv_bfloat16 g_hnp[ML * 2 * D_];
__device__ __nv_bfloat16 g_up [ML * 2 * E_];
__device__ __nv_bfloat16 g_yp [ML * 2 * E_];
__device__ __nv_bfloat16 g_dtA[ML * 128];        // dt_r pair, Kpad=64

// bf16 hi|lo pair weights (per-layer, converted on the fly)
__device__ __nv_bfloat16 g_win [2 * E_ * 2 * D_];
__device__ __nv_bfloat16 g_wx  [SSMW * 2 * E_];
__device__ __nv_bfloat16 g_wdt [E_ * 128];
__device__ __nv_bfloat16 g_wout[D_ * 2 * E_];

// ---------------- fp32 -> bf16 hi/lo pair conversion ----------------
__global__ void cvt_pair(const float* __restrict__ in, int lda, int Kin, int Kpad,
                         int R, __nv_bfloat16* __restrict__ out)
{
    int idx = blockIdx.x * blockDim.x + threadIdx.x;
    if (idx >= R * Kpad) return;
    int r = idx / Kpad, k = idx % Kpad;
    float v = (k < Kin) ? in[(size_t)r * lda + k] : 0.f;
    __nv_bfloat16 hi = __float2bfloat16(v);
    float lo = v - __bfloat162float(hi);
    out[(size_t)r * 2 * Kpad + k]        = hi;
    out[(size_t)r * 2 * Kpad + Kpad + k] = __float2bfloat16(lo);
}

// ---------------- RMSNorm (fp32 out, final layer) ----------------
__global__ void rmsnorm_kernel(const float* __restrict__ in,
                               const float* __restrict__ w,
                               float* __restrict__ out)
{
    int row = blockIdx.x;
    const float* x = in + (size_t)row * D_;
    int t = threadIdx.x;
    float v[3];
    float s = 0.f;
    #pragma unroll
    for (int i = 0; i < 3; i++) { v[i] = x[t + i * 256]; s += v[i] * v[i]; }
    __shared__ float red[256];
    red[t] = s; __syncthreads();
    #pragma unroll
    for (int off = 128; off > 0; off >>= 1) {
        if (t < off) red[t] += red[t + off];
        __syncthreads();
    }
    float scale = rsqrtf(red[0] * (1.0f / D_) + 1e-5f);
    #pragma unroll
    for (int i = 0; i < 3; i++) {
        int d = t + i * 256;
        out[(size_t)row * D_ + d] = v[i] * scale * w[d];
    }
}

// ---------------- RMSNorm emitting bf16 pair ----------------
__global__ void rmsnorm_pair_kernel(const float* __restrict__ in,
                                    const float* __restrict__ w,
                                    __nv_bfloat16* __restrict__ outp)
{
    int row = blockIdx.x;
    const float* x = in + (size_t)row * D_;
    int t = threadIdx.x;
    float v[3];
    float s = 0.f;
    #pragma unroll
    for (int i = 0; i < 3; i++) { v[i] = x[t + i * 256]; s += v[i] * v[i]; }
    __shared__ float red[256];
    red[t] = s; __syncthreads();
    #pragma unroll
    for (int off = 128; off > 0; off >>= 1) {
        if (t < off) red[t] += red[t + off];
        __syncthreads();
    }
    float scale = rsqrtf(red[0] * (1.0f / D_) + 1e-5f);
    #pragma unroll
    for (int i = 0; i < 3; i++) {
        int d = t + i * 256;
        float val = v[i] * scale * w[d];
        __nv_bfloat16 hi = __float2bfloat16(val);
        float lo = val - __bfloat162float(hi);
        outp[(size_t)row * 2 * D_ + d]      = hi;
        outp[(size_t)row * 2 * D_ + D_ + d] = __float2bfloat16(lo);
    }
}

// ---------------- bf16 tensor-core NT GEMM, hi/lo 3-segment K ------------
// A[M][2*Ksz], B[N][2*Ksz]  (both [hi|lo] along K). Effective K = 3*Ksz:
//   seg0: Ahi*Bhi, seg1: Alo*Bhi, seg2: Ahi*Blo    (ll term dropped)
// modes: 0 store, 1 softplus+bias, 2 C+=, 4 store ssm + emit dtA pair
#define BM 128
#define BN 128
#define BK 32
#define STG 3
#define SROW 40    /* bf16 row stride in smem: 80B = 5 x 16B chunks -> conflict-free ldmatrix */

__device__ __forceinline__ void cp16b(__nv_bfloat16* dst_smem, const __nv_bfloat16* src, bool pred) {
    uint32_t d = (uint32_t)__cvta_generic_to_shared(dst_smem);
    int sz = pred ? 16 : 0;
    asm volatile("cp.async.cg.shared.global [%0], [%1], 16, %2;"
                 :: "r"(d), "l"(src), "r"(sz));
}

__device__ __forceinline__ void ldm4(uint32_t& r0, uint32_t& r1, uint32_t& r2, uint32_t& r3,
                                     const __nv_bfloat16* p) {
    uint32_t a = (uint32_t)__cvta_generic_to_shared(p);
    asm volatile("ldmatrix.sync.aligned.m8n8.x4.shared.b16 {%0,%1,%2,%3}, [%4];"
                 : "=r"(r0), "=r"(r1), "=r"(r2), "=r"(r3) : "r"(a));
}

__device__ __forceinline__ void mma_bf16(float* c, const uint32_t* a, const uint32_t* b) {
    asm volatile(
        "mma.sync.aligned.m16n8k16.row.col.f32.bf16.bf16.f32 "
        "{%0,%1,%2,%3}, {%4,%5,%6,%7}, {%8,%9}, {%0,%1,%2,%3};"
        : "+f"(c[0]), "+f"(c[1]), "+f"(c[2]), "+f"(c[3])
        : "r"(a[0]), "r"(a[1]), "r"(a[2]), "r"(a[3]),
          "r"(b[0]), "r"(b[1]));
}

__global__ void __launch_bounds__(256, 2)
gemm_bf16(const __nv_bfloat16* __restrict__ A,
          const __nv_bfloat16* __restrict__ B,
          float* __restrict__ C, int ldc,
          int M, int N, int Ksz,
          int mode, const float* __restrict__ bias,
          __nv_bfloat16* __restrict__ dtA)
{
    extern __shared__ __nv_bfloat16 sm[];
    __nv_bfloat16* As = sm;                     // [STG][BM][SROW]
    __nv_bfloat16* Bs = sm + STG * BM * SROW;   // [STG][BN][SROW]

    int tid  = threadIdx.x;
    int bm   = blockIdx.y * BM;
    int bn   = blockIdx.x * BN;
    int warp = tid >> 5, lane = tid & 31;
    int wm = warp & 3, wn = warp >> 2;       // 4x2 warps -> 32x64 per warp
    int i8 = lane & 7, wh = lane >> 3;

    int aRow = wm * 32 + i8 + (wh & 1) * 8;  // + mt*16
    int aCol = (wh >> 1) * 8;                // + kk
    int bRow = wn * 64 + i8 + (wh >> 1) * 8; // + p*16
    int bCol = (wh & 1) * 8;                 // + kk

    int ldab = 2 * Ksz;
    int lrow = tid >> 1;                     // 0..127
    int lcol = (tid & 1) * 16;               // two 16B chunks: +0, +8

    int tseg   = Ksz / BK;
    int ntiles = 3 * tseg;

    float acc[2][8][4];
    #pragma unroll
    for (int i = 0; i < 2; i++)
        #pragma unroll
        for (int j = 0; j < 8; j++)
            #pragma unroll
            for (int k = 0; k < 4; k++) acc[i][j][k] = 0.f;

    auto issue = [&](int s, int t) {
        int seg = t / tseg;
        int r   = t * BK - seg * Ksz;
        int Ak  = (seg == 1) ? Ksz + r : r;
        int Bk  = (seg == 2) ? Ksz + r : r;
        __nv_bfloat16* as = As + (s * BM + lrow) * SROW + lcol;
        const __nv_bfloat16* ag = A + (size_t)(bm + lrow) * ldab + Ak + lcol;
        cp16b(as,     ag,     true);
        cp16b(as + 8, ag + 8, true);
        __nv_bfloat16* bs = Bs + (s * BN + lrow) * SROW + lcol;
        const __nv_bfloat16* bg = B + (size_t)(bn + lrow) * ldab + Bk + lcol;
        bool p = (bn + lrow) < N;
        cp16b(bs,     bg,     p);
        cp16b(bs + 8, bg + 8, p);
    };

    #pragma unroll
    for (int s = 0; s < STG - 1; s++) {
        if (s < ntiles) issue(s, s);
        asm volatile("cp.async.commit_group;");
    }

    for (int t = 0; t < ntiles; t++) {
        asm volatile("cp.async.wait_group %0;" :: "n"(STG - 2));
        __syncthreads();

        int tn = t + STG - 1;
        if (tn < ntiles) issue(tn % STG, tn);
        asm volatile("cp.async.commit_group;");

        int s = t % STG;
        const __nv_bfloat16* AsS = As + s * BM * SROW;
        const __nv_bfloat16* BsS = Bs + s * BN * SROW;

        #pragma unroll
        for (int kk = 0; kk < BK; kk += 16) {
            uint32_t af[2][4];
            #pragma unroll
            for (int mt = 0; mt < 2; mt++)
                ldm4(af[mt][0], af[mt][1], af[mt][2], af[mt][3],
                     AsS + (aRow + mt * 16) * SROW + kk + aCol);
            uint32_t bf[8][2];
            #pragma unroll
            for (int p = 0; p < 4; p++) {
                uint32_t r0, r1, r2, r3;
                ldm4(r0, r1, r2, r3, BsS + (bRow + p * 16) * SROW + kk + bCol);
                bf[2 * p][0] = r0; bf[2 * p][1] = r1;
                bf[2 * p + 1][0] = r2; bf[2 * p + 1][1] = r3;
            }
            #pragma unroll
            for (int mt = 0; mt < 2; mt++)
                #pragma unroll
                for (int nt = 0; nt < 8; nt++)
                    mma_bf16(acc[mt][nt], af[mt], bf[nt]);
        }
        __syncthreads();
    }

    // epilogue
    int gidr = lane >> 2, tg = lane & 3;
    #pragma unroll
    for (int mt = 0; mt < 2; mt++) {
        #pragma unroll
        for (int nt = 0; nt < 8; nt++) {
            int r0 = bm + wm * 32 + mt * 16 + gidr;
            int cn = bn + wn * 64 + nt * 8 + tg * 2;
            #pragma unroll
            for (int k = 0; k < 4; k++) {
                int r  = r0 + (k >> 1) * 8;
                int cc = cn + (k & 1);
                float v = acc[mt][nt][k];
                size_t off = (size_t)r * ldc + cc;
                if (mode == 0) {
                    if (cc < N) C[off] = v;
                } else if (mode == 1) {
                    if (cc < N) {
                        v += bias[cc];
                        v = (v > 20.f) ? v : log1pf(__expf(v));
                        C[off] = v;
                    }
                } else if (mode == 2) {
                    if (cc < N) C[off] += v;
                } else { // mode 4: ssm store + dt_r pair (Kpad 64)
                    if (cc < N) C[off] = v;
                    if (cc < 64) {
                        float vv = (cc < DTR_) ? v : 0.f;
                        __nv_bfloat16 hi = __float2bfloat16(vv);
                        float lo = vv - __bfloat162float(hi);
                        dtA[(size_t)r * 128 + cc]      = hi;
                        dtA[(size_t)r * 128 + 64 + cc] = __float2bfloat16(lo);
                    }
                }
            }
        }
    }
}

// ---------------- causal depthwise conv (K=4) + SiLU, emits fp32 + pair --
__global__ void conv_silu_kernel(const float* __restrict__ proj,
                                 const float* __restrict__ cw,
                                 const float* __restrict__ cb,
                                 float* __restrict__ u,
                                 __nv_bfloat16* __restrict__ up)
{
    int idx = blockIdx.x * blockDim.x + threadIdx.x;
    if (idx >= ML * E_) return;
    int e = idx % E_;
    int r = idx / E_;
    int l = r % L_;
    float acc = cb[e];
    #pragma unroll
    for (int j = 0; j < K_; j++) {
        int t = l - (K_ - 1) + j;
        if (t >= 0)
            acc += proj[(size_t)(r - (K_ - 1) + j) * (2 * E_) + e] * cw[e * K_ + j];
    }
    float v = acc / (1.f + __expf(-acc));
    u[idx] = v;
    __nv_bfloat16 hi = __float2bfloat16(v);
    float lo = v - __bfloat162float(hi);
    up[(size_t)r * 2 * E_ + e]      = hi;
    up[(size_t)r * 2 * E_ + E_ + e] = __float2bfloat16(lo);
}

// ---------------- selective scan: 16-lane group per (b,e), emits y pair --
__global__ void scan_kernel(const float* __restrict__ dtb,
                            const float* __restrict__ ssm,
                            const float* __restrict__ ub,
                            const float* __restrict__ proj,
                            const float* __restrict__ A_log,
                            const float* __restrict__ Dsk,
                            __nv_bfloat16* __restrict__ yp)
{
    int g = blockIdx.x * (blockDim.x / 16) + (threadIdx.x / 16);
    int lane = threadIdx.x & 15;
    if (g >= B_ * E_) return;
    int b = g / E_;
    int e = g % E_;

    float A  = -__expf(A_log[e * N_ + lane]);
    float Dp = Dsk[e];
    float s  = 0.f;

    size_t base_be = (size_t)b * L_ * E_ + e;
    size_t base_bs = (size_t)b * L_ * SSMW;

    for (int t = 0; t < L_; t++) {
        size_t off = base_be + (size_t)t * E_;
        float dt = dtb[off];
        float uu = ub[off];
        const float* sp = ssm + base_bs + (size_t)t * SSMW;
        float Bv = sp[DTR_ + lane];
        float Cv = sp[DTR_ + N_ + lane];

        float dA = __expf(dt * A);
        s = s * dA + dt * Bv * uu;

        float p = s * Cv;
        p += __shfl_xor_sync(0xffffffffu, p, 8, 16);
        p += __shfl_xor_sync(0xffffffffu, p, 4, 16);
        p += __shfl_xor_sync(0xffffffffu, p, 2, 16);
        p += __shfl_xor_sync(0xffffffffu, p, 1, 16);

        if (lane == 0) {
            float gate = proj[(size_t)(b * L_ + t) * (2 * E_) + E_ + e];
            float gs = gate / (1.f + __expf(-gate));
            float v = (p + uu * Dp) * gs;
            __nv_bfloat16 hi = __float2bfloat16(v);
            float lo = v - __bfloat162float(hi);
            size_t rr = (size_t)(b * L_ + t) * 2 * E_;
            yp[rr + e]      = hi;
            yp[rr + E_ + e] = __float2bfloat16(lo);
        }
    }
}

// ---------------- launch -------------------------------------------------
extern "C" void kernel_launch(void* const* d_in, const int* in_sizes, int n_in,
                              void* d_out, int out_size)
{
    const float* x      = (const float*)d_in[0];
    const float* norm_w = (const float*)d_in[1];
    const float* in_w   = (const float*)d_in[2];
    const float* conv_w = (const float*)d_in[3];
    const float* conv_b = (const float*)d_in[4];
    const float* x_w    = (const float*)d_in[5];
    const float* dt_w   = (const float*)d_in[6];
    const float* dt_b   = (const float*)d_in[7];
    const float* A_log  = (const float*)d_in[8];
    const float* Dsk    = (const float*)d_in[9];
    const float* out_w  = (const float*)d_in[10];
    const float* fin_w  = (const float*)d_in[11];
    float* out = (float*)d_out;

    float *h, *proj, *u, *ssm, *dt;
    __nv_bfloat16 *hnp, *up, *yp, *dtA, *win, *wx, *wdt, *wout;
    cudaGetSymbolAddress((void**)&h,    g_h);
    cudaGetSymbolAddress((void**)&proj, g_proj);
    cudaGetSymbolAddress((void**)&u,    g_u);
    cudaGetSymbolAddress((void**)&ssm,  g_ssm);
    cudaGetSymbolAddress((void**)&dt,   g_dt);
    cudaGetSymbolAddress((void**)&hnp,  g_hnp);
    cudaGetSymbolAddress((void**)&up,   g_up);
    cudaGetSymbolAddress((void**)&yp,   g_yp);
    cudaGetSymbolAddress((void**)&dtA,  g_dtA);
    cudaGetSymbolAddress((void**)&win,  g_win);
    cudaGetSymbolAddress((void**)&wx,   g_wx);
    cudaGetSymbolAddress((void**)&wdt,  g_wdt);
    cudaGetSymbolAddress((void**)&wout, g_wout);

    int smem = STG * (BM + BN) * SROW * (int)sizeof(__nv_bfloat16);
    cudaFuncSetAttribute(gemm_bf16, cudaFuncAttributeMaxDynamicSharedMemorySize, smem);

    cudaMemcpyAsync(h, x, sizeof(float) * ML * D_, cudaMemcpyDeviceToDevice);

    for (int l = 0; l < NL; l++) {
        // weight conversions for this layer
        cvt_pair<<<(2 * E_ * D_ + 255) / 256, 256>>>(
            in_w + (size_t)l * 2 * E_ * D_, D_, D_, D_, 2 * E_, win);
        cvt_pair<<<(SSMW * E_ + 255) / 256, 256>>>(
            x_w + (size_t)l * SSMW * E_, E_, E_, E_, SSMW, wx);
        cvt_pair<<<(E_ * 64 + 255) / 256, 256>>>(
            dt_w + (size_t)l * E_ * DTR_, DTR_, DTR_, 64, E_, wdt);
        cvt_pair<<<(D_ * E_ + 255) / 256, 256>>>(
            out_w + (size_t)l * D_ * E_, E_, E_, E_, D_, wout);

        rmsnorm_pair_kernel<<<ML, 256>>>(h, norm_w + (size_t)l * D_, hnp);

        // proj = hn @ in_w^T   (M=4096, N=3072, Ksz=768)
        gemm_bf16<<<dim3(2 * E_ / BN, ML / BM), 256, smem>>>(
            hnp, win, proj, 2 * E_, ML, 2 * E_, D_, 0, nullptr, nullptr);

        conv_silu_kernel<<<(ML * E_ + 255) / 256, 256>>>(
            proj, conv_w + (size_t)l * E_ * K_, conv_b + (size_t)l * E_, u, up);

        // ssm = u @ x_w^T      (M=4096, N=80, Ksz=1536); also emits dt_r pair
        gemm_bf16<<<dim3(1, ML / BM), 256, smem>>>(
            up, wx, ssm, SSMW, ML, SSMW, E_, 4, nullptr, dtA);

        // dt = softplus(dt_r @ dt_w^T + dt_b)  (M=4096, N=1536, Ksz=64)
        gemm_bf16<<<dim3(E_ / BN, ML / BM), 256, smem>>>(
            dtA, wdt, dt, E_, ML, E_, 64, 1, dt_b + (size_t)l * E_, nullptr);

        scan_kernel<<<(B_ * E_) / 16, 256>>>(
            dt, ssm, u, proj,
            A_log + (size_t)l * E_ * N_, Dsk + (size_t)l * E_, yp);

        // h += y @ out_w^T     (M=4096, N=768, Ksz=1536)
        gemm_bf16<<<dim3(D_ / BN, ML / BM), 256, smem>>>(
            yp, wout, h, D_, ML, D_, E_, 2, nullptr, nullptr);
    }

    rmsnorm_kernel<<<ML, 256>>>(h, fin_w, out);
}